// round 15
// baseline (speedup 1.0000x reference)
#include <cuda_runtime.h>
#include <cuda_fp16.h>

#define NN 100000
#define EE 3200000
#define F_IN 512
#define H1 4
#define C1 8
#define D1 32   // H1*C1
#define D2 8    // num classes
#define ETOT (EE + NN)

typedef unsigned long long ull;

// -------- scratch (device globals; no allocation allowed) --------
__device__ int     g_deg[NN];          // zero-init by loader; re-zeroed each run
__device__ int     g_off[NN];
__device__ int     g_bsum[128];
__device__ int     g_rank[EE];         // within-destination rank (0-based)
__device__ int     g_srcs[ETOT];
__device__ __half  g_xp1h[NN * D1];    // layer-1 features, fp16 (gather-only)
__device__ __half2 g_es1h[NN * H1];    // {exp(as), exp(0.2as)} fp16 (gathered)
__device__ float2  g_ed1[NN * H1];     // dst-side, fp32 (per-warp broadcast)
__device__ float   g_h[NN * D1];       // layer-1 aggregate (normalized, fp32)
__device__ uint4   g_rec2[NN * 2];     // layer-2 packed record: [2n]=xp fp16x8, [2n+1].x=es half2
__device__ float2  g_ed2[NN];          // layer-2 dst-side, fp32

// -------- streams/events for capture fork-join (no device mem) --------
static cudaStream_t g_s1;
static cudaEvent_t g_ev0, g_ev1;
namespace {
struct InitStreams {
    InitStreams() {
        cudaStreamCreateWithFlags(&g_s1, cudaStreamNonBlocking);
        cudaEventCreateWithFlags(&g_ev0, cudaEventDisableTiming);
        cudaEventCreateWithFlags(&g_ev1, cudaEventDisableTiming);
    }
} s_initStreams;
}

// pack two floats into bf16x2: {hi half = hi_elem, lo half = lo_elem}
__device__ __forceinline__ unsigned pack_bf16x2(float hi_elem, float lo_elem) {
    unsigned d;
    asm("cvt.rn.bf16x2.f32 %0, %1, %2;" : "=r"(d) : "f"(hi_elem), "f"(lo_elem));
    return d;
}
// split (f0,f1) into hi/lo bf16x2 pairs (lo = residual)
__device__ __forceinline__ void split_pair(float f0, float f1, unsigned& hi, unsigned& lo) {
    hi = pack_bf16x2(f1, f0);
    float h0 = __uint_as_float(hi << 16);
    float h1 = __uint_as_float(hi & 0xffff0000u);
    lo = pack_bf16x2(f1 - h1, f0 - h0);
}

__device__ __forceinline__ void mma16816(float* c, unsigned a0, unsigned a1,
                                         unsigned a2, unsigned a3,
                                         unsigned b0, unsigned b1) {
    asm volatile(
        "mma.sync.aligned.m16n8k16.row.col.f32.bf16.bf16.f32 "
        "{%0,%1,%2,%3}, {%4,%5,%6,%7}, {%8,%9}, {%0,%1,%2,%3};"
        : "+f"(c[0]), "+f"(c[1]), "+f"(c[2]), "+f"(c[3])
        : "r"(a0), "r"(a1), "r"(a2), "r"(a3), "r"(b0), "r"(b1));
}

// ================= CSR build =================
// histogram with returning atomic: records each edge's within-dst rank (0-based)
__global__ void hist_kernel(const int* __restrict__ ei) {
    int e = blockIdx.x * blockDim.x + threadIdx.x;
    if (e < EE) g_rank[e] = atomicAdd(&g_deg[ei[EE + e]], 1);
}

// 98 blocks x 256 threads x 4 items; adds +1 self-loop; re-zeroes g_deg for replay
__global__ __launch_bounds__(256) void scan_local_kernel() {
    __shared__ int ssum[256];
    int b = blockIdx.x, t = threadIdx.x;
    int base = b * 1024 + t * 4;
    int v[4];
#pragma unroll
    for (int j = 0; j < 4; j++) {
        if (base + j < NN) { v[j] = g_deg[base + j] + 1; g_deg[base + j] = 0; }
        else v[j] = 0;
    }
    int run = 0;
#pragma unroll
    for (int j = 0; j < 4; j++) { int tmp = v[j]; v[j] = run; run += tmp; }
    ssum[t] = run;
    __syncthreads();
#pragma unroll
    for (int s = 1; s < 256; s <<= 1) {
        int x = (t >= s) ? ssum[t - s] : 0;
        __syncthreads();
        ssum[t] += x;
        __syncthreads();
    }
    int toff = (t > 0) ? ssum[t - 1] : 0;
#pragma unroll
    for (int j = 0; j < 4; j++)
        if (base + j < NN) g_off[base + j] = toff + v[j];
    if (t == 255) g_bsum[b] = ssum[255];
}

// merged: per-block rescan of 98 block sums + offset fixup + self-loop placement
__global__ __launch_bounds__(256) void scan_add_kernel() {
    __shared__ int s[128];
    int t = threadIdx.x;
    if (t < 128) s[t] = (t < 98) ? g_bsum[t] : 0;
    __syncthreads();
#pragma unroll
    for (int st = 1; st < 128; st <<= 1) {
        int v = (t < 128 && t >= st) ? s[t - st] : 0;
        __syncthreads();
        if (t < 128) s[t] += v;
        __syncthreads();
    }
    int i = blockIdx.x * blockDim.x + t;
    if (i >= NN) return;
    int b = i >> 10;
    int off = g_off[i] + (b > 0 ? s[b - 1] : 0);
    g_off[i] = off;
    g_srcs[off] = i;       // self-loop at slot 0
}

// atomic-free scatter; +1 skips the self-loop slot
__global__ void scatter_kernel(const int* __restrict__ ei) {
    int e = blockIdx.x * blockDim.x + threadIdx.x;
    if (e >= EE) return;
    int dst = ei[EE + e];
    g_srcs[g_off[dst] + 1 + g_rank[e]] = ei[e];
}

// ================= GEMM1: split-bf16 tensor MMA + fused att1, fp16 store =========
// block 256 = 8 warps x 16 rows = 128 rows; each warp does all 32 cols (4 n-tiles)
__global__ __launch_bounds__(256) void gemm1_kernel(const float* __restrict__ x,
                                                    const float* __restrict__ W,
                                                    const float* __restrict__ att_src,
                                                    const float* __restrict__ att_dst) {
    __shared__ unsigned xa_hi[128][18], xa_lo[128][18]; // [row][kpair], pad 18
    __shared__ unsigned wb_hi[16][40],  wb_lo[16][40];  // [kpair][col], pad 40
    __shared__ float s_as[32], s_ad[32];
    int t = threadIdx.x;
    int warp = t >> 5, lane = t & 31;
    int g = lane >> 2, tid = lane & 3;
    int row0 = blockIdx.x * 128;
    int wrow = row0 + warp * 16;
    if (t < 32) { s_as[t] = att_src[t]; s_ad[t] = att_dst[t]; }

    float c[4][4];   // [ntile=head][c0..c3]
#pragma unroll
    for (int h = 0; h < 4; h++)
#pragma unroll
        for (int j = 0; j < 4; j++) c[h][j] = 0.f;

    for (int k0 = 0; k0 < F_IN; k0 += 32) {
#pragma unroll
        for (int i = 0; i < 4; i++) {
            int idx = t + 256 * i;       // 0..1023
            int r = idx >> 3;            // row 0..127
            int c4 = idx & 7;            // float4 slot 0..7
            float4 v = make_float4(0.f, 0.f, 0.f, 0.f);
            int grow = row0 + r;
            if (grow < NN) v = *(const float4*)(x + (size_t)grow * F_IN + k0 + c4 * 4);
            unsigned hi, lo;
            split_pair(v.x, v.y, hi, lo);
            xa_hi[r][2 * c4] = hi; xa_lo[r][2 * c4] = lo;
            split_pair(v.z, v.w, hi, lo);
            xa_hi[r][2 * c4 + 1] = hi; xa_lo[r][2 * c4 + 1] = lo;
        }
#pragma unroll
        for (int i = 0; i < 2; i++) {
            int idx = t + 256 * i;       // 0..511
            int kp = idx >> 5, n = idx & 31;
            float w0 = W[(k0 + 2 * kp) * 32 + n];
            float w1 = W[(k0 + 2 * kp + 1) * 32 + n];
            unsigned hi, lo;
            split_pair(w0, w1, hi, lo);
            wb_hi[kp][n] = hi; wb_lo[kp][n] = lo;
        }
        __syncthreads();
#pragma unroll
        for (int ks = 0; ks < 2; ks++) { // 2 k-steps of 16
            int kb = ks * 8;
            int r0 = warp * 16 + g;
            unsigned ah0 = xa_hi[r0][kb + tid],     ah1 = xa_hi[r0 + 8][kb + tid];
            unsigned ah2 = xa_hi[r0][kb + tid + 4], ah3 = xa_hi[r0 + 8][kb + tid + 4];
            unsigned al0 = xa_lo[r0][kb + tid],     al1 = xa_lo[r0 + 8][kb + tid];
            unsigned al2 = xa_lo[r0][kb + tid + 4], al3 = xa_lo[r0 + 8][kb + tid + 4];
#pragma unroll
            for (int h = 0; h < 4; h++) {
                unsigned bh0 = wb_hi[kb + tid][h * 8 + g];
                unsigned bh1 = wb_hi[kb + tid + 4][h * 8 + g];
                unsigned bl0 = wb_lo[kb + tid][h * 8 + g];
                unsigned bl1 = wb_lo[kb + tid + 4][h * 8 + g];
                mma16816(c[h], ah0, ah1, ah2, ah3, bh0, bh1);  // hi*hi
                mma16816(c[h], ah0, ah1, ah2, ah3, bl0, bl1);  // hi*lo
                mma16816(c[h], al0, al1, al2, al3, bh0, bh1);  // lo*hi
            }
        }
        __syncthreads();
    }

    // epilogue: fp16 feature stores + per-head att dots (quad reduce)
    int rg = wrow + g, rg8 = wrow + g + 8;
    float tas0[4], tad0[4], tas1[4], tad1[4];
#pragma unroll
    for (int h = 0; h < 4; h++) {
        float w0 = s_as[h * 8 + tid * 2], w1 = s_as[h * 8 + tid * 2 + 1];
        float d0 = s_ad[h * 8 + tid * 2], d1 = s_ad[h * 8 + tid * 2 + 1];
        float pas0 = c[h][0] * w0 + c[h][1] * w1;
        float pad0 = c[h][0] * d0 + c[h][1] * d1;
        float pas1 = c[h][2] * w0 + c[h][3] * w1;
        float pad1 = c[h][2] * d0 + c[h][3] * d1;
#pragma unroll
        for (int m = 1; m < 4; m <<= 1) {
            pas0 += __shfl_xor_sync(0xffffffffu, pas0, m);
            pad0 += __shfl_xor_sync(0xffffffffu, pad0, m);
            pas1 += __shfl_xor_sync(0xffffffffu, pas1, m);
            pad1 += __shfl_xor_sync(0xffffffffu, pad1, m);
        }
        tas0[h] = pas0; tad0[h] = pad0; tas1[h] = pas1; tad1[h] = pad1;
        if (rg < NN)
            *(__half2*)(g_xp1h + (size_t)rg * D1 + h * 8 + tid * 2) =
                __floats2half2_rn(c[h][0], c[h][1]);
        if (rg8 < NN)
            *(__half2*)(g_xp1h + (size_t)rg8 * D1 + h * 8 + tid * 2) =
                __floats2half2_rn(c[h][2], c[h][3]);
    }
    float vas0 = tas0[0], vad0 = tad0[0], vas1 = tas1[0], vad1 = tad1[0];
    if (tid == 1) { vas0 = tas0[1]; vad0 = tad0[1]; vas1 = tas1[1]; vad1 = tad1[1]; }
    if (tid == 2) { vas0 = tas0[2]; vad0 = tad0[2]; vas1 = tas1[2]; vad1 = tad1[2]; }
    if (tid == 3) { vas0 = tas0[3]; vad0 = tad0[3]; vas1 = tas1[3]; vad1 = tad1[3]; }
    // softmax factorization tables: src side fp16 (gathered), dst side fp32
    if (rg < NN) {
        g_es1h[rg * 4 + tid] = __floats2half2_rn(__expf(vas0), __expf(0.2f * vas0));
        g_ed1[rg * 4 + tid]  = make_float2(__expf(vad0), __expf(0.2f * vad0));
    }
    if (rg8 < NN) {
        g_es1h[rg8 * 4 + tid] = __floats2half2_rn(__expf(vas1), __expf(0.2f * vas1));
        g_ed1[rg8 * 4 + tid]  = make_float2(__expf(vad1), __expf(0.2f * vad1));
    }
}

// ================= layer-1 aggregation: warp per dst, 4 lanes/edge ================
// exp-free edge scores: w = (p = e1s*e1d) > 1 ? p : e2s*e2d   (es fp16, ed fp32)
__global__ __launch_bounds__(256) void agg1_kernel() {
    int w = (blockIdx.x * blockDim.x + threadIdx.x) >> 5;
    if (w >= NN) return;
    int lane = threadIdx.x & 31;
    int g = lane >> 2;     // edge slot 0..7
    int h = lane & 3;      // head
    int beg = g_off[w];
    int end = (w + 1 < NN) ? g_off[w + 1] : ETOT;
    float2 ed = g_ed1[w * 4 + h];
    float a0 = 0.f, a1 = 0.f, a2 = 0.f, a3 = 0.f;
    float a4 = 0.f, a5 = 0.f, a6 = 0.f, a7 = 0.f;
    float den = 0.f;
    for (int i = beg + g; i < end; i += 8) {
        int src = g_srcs[i];
        float2 es = __half22float2(g_es1h[src * 4 + h]);
        float p = es.x * ed.x;
        float s = p > 1.f ? p : es.y * ed.y;
        den += s;
        uint4 raw = *(const uint4*)(g_xp1h + (size_t)src * D1 + h * C1);  // 8 halves
        float2 u0 = __half22float2(*(__half2*)&raw.x);
        float2 u1 = __half22float2(*(__half2*)&raw.y);
        float2 u2 = __half22float2(*(__half2*)&raw.z);
        float2 u3 = __half22float2(*(__half2*)&raw.w);
        a0 += s * u0.x; a1 += s * u0.y; a2 += s * u1.x; a3 += s * u1.y;
        a4 += s * u2.x; a5 += s * u2.y; a6 += s * u3.x; a7 += s * u3.y;
    }
#pragma unroll
    for (int m = 4; m < 32; m <<= 1) {
        den += __shfl_xor_sync(0xffffffffu, den, m);
        a0 += __shfl_xor_sync(0xffffffffu, a0, m);
        a1 += __shfl_xor_sync(0xffffffffu, a1, m);
        a2 += __shfl_xor_sync(0xffffffffu, a2, m);
        a3 += __shfl_xor_sync(0xffffffffu, a3, m);
        a4 += __shfl_xor_sync(0xffffffffu, a4, m);
        a5 += __shfl_xor_sync(0xffffffffu, a5, m);
        a6 += __shfl_xor_sync(0xffffffffu, a6, m);
        a7 += __shfl_xor_sync(0xffffffffu, a7, m);
    }
    if (g == 0) {
        float inv = 1.f / den;
        float* o = g_h + (size_t)w * D1 + h * C1;
        *(float4*)(o)     = make_float4(a0 * inv, a1 * inv, a2 * inv, a3 * inv);
        *(float4*)(o + 4) = make_float4(a4 * inv, a5 * inv, a6 * inv, a7 * inv);
    }
}

// ====== node epilogue: bias + elu + GEMM2 + att2, packed 32B record + ed table ====
__global__ __launch_bounds__(256) void node1_kernel(const float* __restrict__ b1,
                                                    const float* __restrict__ W2,
                                                    const float* __restrict__ as2w,
                                                    const float* __restrict__ ad2w) {
    __shared__ float w2s[D1 * D2];
    __shared__ float b1s[D1];
    __shared__ float a2s[D2], a2d[D2];
    int t = threadIdx.x;
    if (t < D1 * D2) w2s[t] = W2[t];
    if (t < D1) b1s[t] = b1[t];
    if (t < D2) { a2s[t] = as2w[t]; a2d[t] = ad2w[t]; }
    __syncthreads();
    int n = blockIdx.x * blockDim.x + t;
    if (n >= NN) return;
    float h[D1];
#pragma unroll
    for (int k = 0; k < D1; k++) {
        float v = g_h[(size_t)n * D1 + k] + b1s[k];
        h[k] = v > 0.f ? v : expm1f(v);   // elu
    }
    float xp[D2];
#pragma unroll
    for (int c = 0; c < D2; c++) xp[c] = 0.f;
#pragma unroll
    for (int k = 0; k < D1; k++)
#pragma unroll
        for (int c = 0; c < D2; c++) xp[c] += h[k] * w2s[k * D2 + c];
    float as = 0.f, ad = 0.f;
#pragma unroll
    for (int c = 0; c < D2; c++) { as += xp[c] * a2s[c]; ad += xp[c] * a2d[c]; }
    __half2 hx[4];
#pragma unroll
    for (int j = 0; j < 4; j++) hx[j] = __floats2half2_rn(xp[2 * j], xp[2 * j + 1]);
    __half2 esh = __floats2half2_rn(__expf(as), __expf(0.2f * as));
    g_rec2[2 * n]     = *(uint4*)hx;                 // 16B features
    g_rec2[2 * n + 1] = make_uint4(*(unsigned*)&esh, 0u, 0u, 0u);  // es + pad
    g_ed2[n] = make_float2(__expf(ad), __expf(0.2f * ad));
}

// ====== layer-2 aggregation: warp per dst, 1-sector packed gather ================
__global__ __launch_bounds__(256) void agg2_kernel(float* __restrict__ out,
                                                   const float* __restrict__ b2) {
    int w = (blockIdx.x * blockDim.x + threadIdx.x) >> 5;
    if (w >= NN) return;
    int lane = threadIdx.x & 31;
    int beg = g_off[w];
    int end = (w + 1 < NN) ? g_off[w + 1] : ETOT;
    float2 ed = g_ed2[w];
    float a0 = 0.f, a1 = 0.f, a2 = 0.f, a3 = 0.f;
    float a4 = 0.f, a5 = 0.f, a6 = 0.f, a7 = 0.f;
    float den = 0.f;
    for (int i = beg + lane; i < end; i += 32) {
        int src = g_srcs[i];
        uint4 raw = g_rec2[2 * src];               // same 32B sector as the es word
        unsigned esb = g_rec2[2 * src + 1].x;
        float2 es = __half22float2(*(__half2*)&esb);
        float p = es.x * ed.x;
        float s = p > 1.f ? p : es.y * ed.y;
        den += s;
        float2 u0 = __half22float2(*(__half2*)&raw.x);
        float2 u1 = __half22float2(*(__half2*)&raw.y);
        float2 u2 = __half22float2(*(__half2*)&raw.z);
        float2 u3 = __half22float2(*(__half2*)&raw.w);
        a0 += s * u0.x; a1 += s * u0.y; a2 += s * u1.x; a3 += s * u1.y;
        a4 += s * u2.x; a5 += s * u2.y; a6 += s * u3.x; a7 += s * u3.y;
    }
#pragma unroll
    for (int m = 1; m < 32; m <<= 1) {
        den += __shfl_xor_sync(0xffffffffu, den, m);
        a0 += __shfl_xor_sync(0xffffffffu, a0, m);
        a1 += __shfl_xor_sync(0xffffffffu, a1, m);
        a2 += __shfl_xor_sync(0xffffffffu, a2, m);
        a3 += __shfl_xor_sync(0xffffffffu, a3, m);
        a4 += __shfl_xor_sync(0xffffffffu, a4, m);
        a5 += __shfl_xor_sync(0xffffffffu, a5, m);
        a6 += __shfl_xor_sync(0xffffffffu, a6, m);
        a7 += __shfl_xor_sync(0xffffffffu, a7, m);
    }
    if (lane == 0) {
        float inv = 1.f / den;
        float* o = out + (size_t)w * D2;
        *(float4*)(o)     = make_float4(a0 * inv + b2[0], a1 * inv + b2[1],
                                        a2 * inv + b2[2], a3 * inv + b2[3]);
        *(float4*)(o + 4) = make_float4(a4 * inv + b2[4], a5 * inv + b2[5],
                                        a6 * inv + b2[6], a7 * inv + b2[7]);
    }
}

extern "C" void kernel_launch(void* const* d_in, const int* in_sizes, int n_in,
                              void* d_out, int out_size) {
    const float* x        = (const float*)d_in[0];
    const int*   ei       = (const int*)d_in[1];
    const float* W1       = (const float*)d_in[2];
    const float* att_src1 = (const float*)d_in[3];
    const float* att_dst1 = (const float*)d_in[4];
    const float* b1       = (const float*)d_in[5];
    const float* W2       = (const float*)d_in[6];
    const float* att_src2 = (const float*)d_in[7];
    const float* att_dst2 = (const float*)d_in[8];
    const float* b2       = (const float*)d_in[9];
    float* out = (float*)d_out;

    const int TB = 256;
    int gN = (NN + TB - 1) / TB;            // 391
    int gE = (EE + TB - 1) / TB;            // 12500 (scalar, 1 edge/thread)
    int gW = (NN * 32 + TB - 1) / TB;       // 12500
    int gG = (NN + 127) / 128;              // 782 (gemm1 blocks)

    // fork: GEMM1 on side stream, CSR build on main stream (independent)
    cudaEventRecord(g_ev0, 0);
    cudaStreamWaitEvent(g_s1, g_ev0, 0);
    gemm1_kernel<<<gG, 256, 0, g_s1>>>(x, W1, att_src1, att_dst1);
    cudaEventRecord(g_ev1, g_s1);

    hist_kernel<<<gE, TB>>>(ei);
    scan_local_kernel<<<98, 256>>>();
    scan_add_kernel<<<gN, TB>>>();
    scatter_kernel<<<gE, TB>>>(ei);

    // join
    cudaStreamWaitEvent(0, g_ev1, 0);
    agg1_kernel<<<gW, TB>>>();
    node1_kernel<<<gN, TB>>>(b1, W2, att_src2, att_dst2);
    agg2_kernel<<<gW, TB>>>(out, b2);
}